// round 10
// baseline (speedup 1.0000x reference)
#include <cuda_runtime.h>
#include <cstdint>

// Fixed shapes per reference: B=256, L=512, N=50000
constexpr int B_SZ   = 256;
constexpr int L_SEQ  = 512;
constexpr int N_LOC  = 50000;
constexpr int HSIZE  = 1024;                 // hash slots (pow2), load factor 0.5
constexpr int NT     = 256;
constexpr int SEGS   = 4;                    // CTAs per row (grid = 1024, single wave)
constexpr int ROW_F4 = N_LOC / 4;            // 12,500 float4 per row
constexpr int CHUNK_F4 = ROW_F4 / SEGS;      // 3,125 float4 per CTA (50 KB)
constexpr int PAD    = 32;                   // 128B padding between row counters

__device__ int g_done[B_SZ * PAD];           // zero-initialized at module load

__global__ __launch_bounds__(NT, 8)
void fused_kernel(const int* __restrict__ loc_seq,
                  const int* __restrict__ mask,
                  const float* __restrict__ rw_p,
                  const float* __restrict__ fw_p,
                  float* __restrict__ out)
{
    const int b   = blockIdx.x >> 2;         // row
    const int q   = blockIdx.x & 3;          // quarter within row
    const int tid = threadIdx.x;

    __shared__ int      h_key[HSIZE];
    __shared__ int      h_cnt[HSIZE];
    __shared__ unsigned h_rec[HSIZE];        // float bits; all values >= 0
    __shared__ int      s_maxcnt;

    float* const row = out + (size_t)b * N_LOC;

    if (q != 0) {
        // ============ sibling: zero own quarter, signal, exit ============
        float4* row4 = reinterpret_cast<float4*>(row);
        const float4 z = make_float4(0.f, 0.f, 0.f, 0.f);
        const int i0 = q * CHUNK_F4;
        #pragma unroll 4
        for (int i = i0 + tid; i < i0 + CHUNK_F4; i += NT)
            row4[i] = z;

        __threadfence();                     // make my zero stores visible gpu-wide
        __syncthreads();                     // all threads fenced
        if (tid == 0)
            atomicAdd(&g_done[b * PAD], 1);
        return;
    }

    // ============ leader (q==0): hash build + own quarter zero + scatter ============
    #pragma unroll 4
    for (int i = tid; i < HSIZE; i += NT) {
        h_key[i] = -1;
        h_cnt[i] = 0;
        h_rec[i] = 0u;
    }
    if (tid == 0) s_maxcnt = 0;
    __syncthreads();

    const float l2rw = log2f(*rw_p);

    const int2* lrow = reinterpret_cast<const int2*>(loc_seq + (size_t)b * L_SEQ);
    const int2* mrow = reinterpret_cast<const int2*>(mask    + (size_t)b * L_SEQ);
    const int2 lk = lrow[tid];
    const int2 mk = mrow[tid];

    // zero own quarter (LSU) interleaved with hash build (smem pipe)
    {
        float4* row4 = reinterpret_cast<float4*>(row);
        const float4 z = make_float4(0.f, 0.f, 0.f, 0.f);
        #pragma unroll 4
        for (int i = tid; i < CHUNK_F4; i += NT)
            row4[i] = z;
    }

    #pragma unroll
    for (int j = 0; j < 2; j++) {
        const int t   = 2 * tid + j;
        const int key = (j == 0) ? lk.x : lk.y;
        const int m   = (j == 0) ? mk.x : mk.y;
        const float rec = m ? exp2f((float)(L_SEQ - 1 - t) * l2rw) : 0.0f;

        unsigned h = ((unsigned)key * 2654435761u) & (HSIZE - 1);
        for (;;) {
            int cur = h_key[h];
            if (cur == key) break;
            if (cur == -1) {
                int prev = atomicCAS(&h_key[h], -1, key);
                if (prev == -1 || prev == key) break;
            }
            h = (h + 1) & (HSIZE - 1);
        }
        atomicAdd(&h_cnt[h], m);
        atomicMax(&h_rec[h], __float_as_uint(rec));
    }
    __syncthreads();

    // block reduce: max frequency count (4 slots per thread)
    int mf = 0;
    #pragma unroll 4
    for (int i = tid; i < HSIZE; i += NT) mf = max(mf, h_cnt[i]);
    #pragma unroll
    for (int o = 16; o > 0; o >>= 1) mf = max(mf, __shfl_xor_sync(0xFFFFFFFFu, mf, o));
    if ((tid & 31) == 0) atomicMax(&s_maxcnt, mf);

    // wait for the 3 siblings (sole consumer resets flag -> replay-safe; only
    // 256 leader CTAs can ever spin, far below resident capacity -> no deadlock)
    if (tid == 0) {
        volatile int* dp = &g_done[b * PAD];
        while (*dp != SEGS - 1) __nanosleep(32);
        __threadfence();                     // acquire: siblings' zeros visible
        *dp = 0;                             // reset for next graph replay
    }
    __syncthreads();

    const float inv = (*fw_p) / fmaxf((float)s_maxcnt, 1.0f);

    // scatter final values directly from the smem hash (whole row)
    #pragma unroll 4
    for (int i = tid; i < HSIZE; i += NT) {
        const int key = h_key[i];
        if (key >= 0) {
            row[key] = __uint_as_float(h_rec[i]) + (float)h_cnt[i] * inv;
        }
    }
}

extern "C" void kernel_launch(void* const* d_in, const int* in_sizes, int n_in,
                              void* d_out, int out_size)
{
    const int*   loc_seq = (const int*)  d_in[0];   // (B, L) int32
    const int*   mask    = (const int*)  d_in[1];   // (B, L) int32
    const float* rw      = (const float*)d_in[2];   // scalar
    const float* fw      = (const float*)d_in[3];   // scalar
    float*       out     = (float*)d_out;           // (B, N) float32

    fused_kernel<<<B_SZ * SEGS, NT>>>(loc_seq, mask, rw, fw, out);
}